// round 10
// baseline (speedup 1.0000x reference)
#include <cuda_runtime.h>
#include <cuda_fp16.h>
#include <math.h>
#include <stdint.h>

constexpr int CB   = 2;
constexpr int CL   = 1024;
constexpr int CD   = 1024;
constexpr int CDIN = 2048;
constexpr int CN   = 16;
constexpr int CR   = 64;
constexpr int CK   = 4;
constexpr int CML  = CB * CL;      // 2048
constexpr int CXD  = CR + 2 * CN;  // 96
constexpr int KSPL = 8;            // split-K factor for G2
constexpr float CLN_EPS = 1e-5f;

// ---------------- scratch (device globals; no allocation) ----------------
__device__ float g_xz   [CML * (2*CDIN)];
__device__ float g_xc   [CML * CDIN];
__device__ float g_xdbl [CML * CXD];
__device__ float g_delta[CML * CDIN];
__device__ float g_pre  [CML * CD];
__device__ float g_part [KSPL * CML * CXD];   // split-K partials for G2

// fp16 packed planes (u32 = two fp16 along K)
__device__ uint32_t g_xp    [CML * (CD/2)];                                  // x single plane
__device__ uint32_t g_Winp_h[(2*CDIN) * (CD/2)],  g_Winp_l[(2*CDIN) * (CD/2)];
__device__ uint32_t g_Wxp_h [CXD * (CDIN/2)],     g_Wxp_l [CXD * (CDIN/2)];
__device__ uint32_t g_Wdtp_h[CDIN * (CR/2)],      g_Wdtp_l[CDIN * (CR/2)];
__device__ uint32_t g_Woutp_h[CD * (CDIN/2)],     g_Woutp_l[CD * (CDIN/2)];
// activation planes: single fp16 (u16)
__device__ uint16_t g_xcp [CML * CDIN];
__device__ uint16_t g_xdp [CML * CXD];
__device__ uint16_t g_ygp [CML * CDIN];

// ---------------- helpers ----------------
__device__ __forceinline__ uint16_t to_fp16(float x)
{
    return __half_as_ushort(__float2half_rn(x));
}

__device__ __forceinline__ void split_fp16(float x, uint16_t& h, uint16_t& l)
{
    __half hh = __float2half_rn(x);
    float r = x - __half2float(hh);
    __half ll = __float2half_rn(r);
    h = __half_as_ushort(hh);
    l = __half_as_ushort(ll);
}

__device__ __forceinline__ void mma_fp16(float* acc, const uint32_t* a, const uint32_t* b)
{
    asm volatile(
        "mma.sync.aligned.m16n8k16.row.col.f32.f16.f16.f32 "
        "{%0,%1,%2,%3}, {%4,%5,%6,%7}, {%8,%9}, {%0,%1,%2,%3};\n"
        : "+f"(acc[0]), "+f"(acc[1]), "+f"(acc[2]), "+f"(acc[3])
        : "r"(a[0]), "r"(a[1]), "r"(a[2]), "r"(a[3]), "r"(b[0]), "r"(b[1]));
}

__device__ __forceinline__ void cp_async16(uint32_t smem_addr, const void* gptr)
{
    asm volatile("cp.async.cg.shared.global [%0], [%1], 16;\n" :: "r"(smem_addr), "l"(gptr));
}

__device__ __forceinline__ uint32_t smem_u32(const void* p)
{
    uint32_t a;
    asm("{ .reg .u64 t; cvta.to.shared.u64 t, %1; cvt.u32.u64 %0, t; }" : "=r"(a) : "l"(p));
    return a;
}

// ---------------- pack x: fp16 single plane ----------------
__global__ void pack_x_kernel(const float* __restrict__ x)
{
    int i = blockIdx.x * blockDim.x + threadIdx.x;
    if (i >= CML * (CD/2)) return;
    uint16_t h0 = to_fp16(x[2*i]);
    uint16_t h1 = to_fp16(x[2*i + 1]);
    g_xp[i] = (uint32_t)h0 | ((uint32_t)h1 << 16);
}

// ---------------- transpose-pack weight: W[K][N] -> hi/lo fp16 [N][K/2] u32 ----------------
__global__ void pack_w_kernel(const float* __restrict__ W, int K, int N,
                              uint32_t* __restrict__ oh, uint32_t* __restrict__ ol)
{
    __shared__ float sm[64][33];
    int k0 = blockIdx.x * 64;
    int n0 = blockIdx.y * 32;
    int t  = threadIdx.x;
    int c  = t & 31;
    int r0 = t >> 5;
    #pragma unroll
    for (int it = 0; it < 8; it++) {
        int r = r0 + it * 8;
        sm[r][c] = W[(size_t)(k0 + r) * N + n0 + c];
    }
    __syncthreads();
    int k2 = t & 31;
    int nn0 = t >> 5;
    #pragma unroll
    for (int it = 0; it < 4; it++) {
        int n = nn0 + it * 8;
        float v0 = sm[2*k2    ][n];
        float v1 = sm[2*k2 + 1][n];
        uint16_t h0, l0, h1, l1;
        split_fp16(v0, h0, l0);
        split_fp16(v1, h1, l1);
        size_t o = (size_t)(n0 + n) * (K/2) + k0/2 + k2;
        oh[o] = (uint32_t)h0 | ((uint32_t)h1 << 16);
        ol[o] = (uint32_t)l0 | ((uint32_t)l1 << 16);
    }
}

// ---------------- fp16 tensor-core GEMM, weights 2-term split ----------------
// C[M,N] = A[M,K] @ (Bh + Bl)[K,N]; A single fp16 plane [M][K/2] u32,
// B planes [N][K/2] u32. BM=BN=128, BK=16, 256 thr, warp tile 64x32.
// 3-stage cp.async pipeline. EPI: 0 plain, 1 softplus(acc+bias[col]).
constexpr int BM = 128, BN = 128;
constexpr int STR = 12;                    // u32 stride per row (conflict-free)
constexpr int PLANE = 128 * STR;           // 1536 u32 per plane
constexpr int STAGE_U = 3 * PLANE;         // A, Bh, Bl
constexpr int NSTG = 3;
constexpr int GEMM_SMEM = NSTG * STAGE_U * 4;   // 55296 bytes

template<int EPI>
__global__ __launch_bounds__(256, 2)
void tgemm4(int M, int N,
            const uint32_t* __restrict__ A_g, int lda2,
            const uint32_t* __restrict__ Bh_g, const uint32_t* __restrict__ Bl_g, int ldb2,
            float* __restrict__ C, int ldc, const float* __restrict__ bias,
            int k2_begin, int ntiles, int zstride)
{
    extern __shared__ uint32_t sm[];

    const int tid  = threadIdx.x;
    const int warp = tid >> 5;
    const int lane = tid & 31;
    const int g    = lane >> 2;
    const int tg   = lane & 3;

    const int row0 = blockIdx.y * BM;
    const int col0 = blockIdx.x * BN;
    const int wm0  = (warp >> 2) * 64;
    const int wn0  = (warp & 3) * 32;

    const int ldRow = tid >> 1;        // 0..127
    const int ldC4  = (tid & 1) * 4;   // 0 or 4

    const int k2b = k2_begin + blockIdx.z * zstride;

    float acc[4][4][4];
    #pragma unroll
    for (int i = 0; i < 4; i++)
        #pragma unroll
        for (int j = 0; j < 4; j++)
            #pragma unroll
            for (int r = 0; r < 4; r++) acc[i][j][r] = 0.f;

    // zero OOB B rows once (loads are guarded, so they stay zero)
    if (N < BN) {
        int nz = BN - N;
        int total = NSTG * 2 * nz * 8;
        for (int idx = tid; idx < total; idx += 256) {
            int lin = idx;
            int w  = lin & 7; lin >>= 3;
            int rq = lin % nz; lin /= nz;
            int pl = lin & 1; lin >>= 1;
            int sq = lin;
            sm[sq * STAGE_U + (1 + pl) * PLANE + (N + rq) * STR + w] = 0;
        }
    }
    __syncthreads();

    auto load_stage = [&](int stg, int kt) {
        uint32_t* base = sm + stg * STAGE_U;
        const size_t aoff = (size_t)(row0 + ldRow) * lda2 + (k2b + kt * 8) + ldC4;
        cp_async16(smem_u32(&base[ldRow * STR + ldC4]), A_g + aoff);
        if (col0 + ldRow < N) {
            const size_t boff = (size_t)(col0 + ldRow) * ldb2 + (k2b + kt * 8) + ldC4;
            cp_async16(smem_u32(&base[PLANE     + ldRow * STR + ldC4]), Bh_g + boff);
            cp_async16(smem_u32(&base[2 * PLANE + ldRow * STR + ldC4]), Bl_g + boff);
        }
    };

    load_stage(0, 0);
    asm volatile("cp.async.commit_group;\n" ::: "memory");
    if (ntiles > 1) {
        load_stage(1, 1);
        asm volatile("cp.async.commit_group;\n" ::: "memory");
    }

    for (int kt = 0; kt < ntiles; kt++) {
        if (kt + 2 < ntiles) {
            load_stage((kt + 2) % NSTG, kt + 2);
            asm volatile("cp.async.commit_group;\n" ::: "memory");
            asm volatile("cp.async.wait_group 2;\n" ::: "memory");
        } else if (kt + 1 < ntiles) {
            asm volatile("cp.async.wait_group 1;\n" ::: "memory");
        } else {
            asm volatile("cp.async.wait_group 0;\n" ::: "memory");
        }
        __syncthreads();

        const uint32_t* Ap = sm + (kt % NSTG) * STAGE_U;
        const uint32_t* Bh = Ap + PLANE;
        const uint32_t* Bl = Ap + 2 * PLANE;

        uint32_t af[4][4];
        #pragma unroll
        for (int mt = 0; mt < 4; mt++) {
            int r = wm0 + mt * 16 + g;
            af[mt][0] = Ap[ r      * STR + tg    ];
            af[mt][1] = Ap[(r + 8) * STR + tg    ];
            af[mt][2] = Ap[ r      * STR + tg + 4];
            af[mt][3] = Ap[(r + 8) * STR + tg + 4];
        }
        uint32_t bfh[4][2], bfl[4][2];
        #pragma unroll
        for (int nt = 0; nt < 4; nt++) {
            int c = wn0 + nt * 8 + g;
            bfh[nt][0] = Bh[c * STR + tg    ];
            bfh[nt][1] = Bh[c * STR + tg + 4];
            bfl[nt][0] = Bl[c * STR + tg    ];
            bfl[nt][1] = Bl[c * STR + tg + 4];
        }
        #pragma unroll
        for (int mt = 0; mt < 4; mt++)
            #pragma unroll
            for (int nt = 0; nt < 4; nt++) {
                mma_fp16(acc[mt][nt], af[mt], bfh[nt]);
                mma_fp16(acc[mt][nt], af[mt], bfl[nt]);
            }
        __syncthreads();
    }

    float* Cz = C + (size_t)blockIdx.z * CML * ldc;

    #pragma unroll
    for (int mt = 0; mt < 4; mt++) {
        int r0 = row0 + wm0 + mt * 16 + g;
        #pragma unroll
        for (int nt = 0; nt < 4; nt++) {
            int c0 = col0 + wn0 + nt * 8 + 2 * tg;
            #pragma unroll
            for (int rr = 0; rr < 2; rr++) {
                int r = r0 + rr * 8;
                #pragma unroll
                for (int cc = 0; cc < 2; cc++) {
                    int c = c0 + cc;
                    if (c < N) {
                        float v = acc[mt][nt][rr * 2 + cc];
                        if (EPI == 1) {
                            v = v + bias[c];
                            v = (v > 20.f) ? v : log1pf(__expf(v));
                        }
                        Cz[(size_t)r * ldc + c] = v;
                    }
                }
            }
        }
    }
}

// ---------------- split-K reduce for G2 -> xdbl fp32 + fp16 plane ----------------
__global__ void reduce_xdbl_kernel()
{
    int i = blockIdx.x * blockDim.x + threadIdx.x;
    if (i >= CML * CXD) return;
    float s = 0.f;
    #pragma unroll
    for (int z = 0; z < KSPL; z++) s += g_part[(size_t)z * CML * CXD + i];
    g_xdbl[i] = s;
    g_xdp[i] = to_fp16(s);
}

// ---------------- causal depthwise conv + SiLU + fp16 pack ----------------
__global__ void conv_silu_kernel(const float* __restrict__ conv_w,
                                 const float* __restrict__ conv_b)
{
    int i = blockIdx.x * blockDim.x + threadIdx.x;
    if (i >= CML * CDIN) return;
    int d  = i & (CDIN - 1);
    int bl = i >> 11;
    int l  = bl & (CL - 1);
    int b  = bl >> 10;

    float acc = conv_b[d];
    #pragma unroll
    for (int k = 0; k < CK; k++) {
        int ll = l - (CK - 1) + k;
        if (ll >= 0) {
            float xin = g_xz[(size_t)(b * CL + ll) * (2 * CDIN) + d];
            acc = fmaf(xin, conv_w[d * CK + k], acc);
        }
    }
    float sig = 1.f / (1.f + __expf(-acc));
    float v = acc * sig;
    g_xc[i] = v;
    g_xcp[i] = to_fp16(v);
}

// ---------------- selective scan (+ skip + gate + fp16 pack epi) ----------------
__global__ __launch_bounds__(128)
void scan_kernel(const float* __restrict__ A_log,
                 const float* __restrict__ D_skip)
{
    int warp = (blockIdx.x * blockDim.x + threadIdx.x) >> 5;
    int lane = threadIdx.x & 31;
    int half = lane >> 4;
    int n    = lane & 15;

    int b = warp >> 10;
    int d = ((warp & 1023) << 1) + half;

    float a_coef = -expf(A_log[d * CN + n]);
    float d_skip = D_skip[d];
    float h = 0.f;

    const size_t bl0 = (size_t)b * CL;
    for (int t = 0; t < CL; t++) {
        size_t bl = bl0 + t;
        float dv = g_delta[bl * CDIN + d];
        float xc = g_xc   [bl * CDIN + d];
        float Bn = g_xdbl [bl * CXD + CR + n];
        float Cn = g_xdbl [bl * CXD + CR + CN + n];

        float dA = __expf(dv * a_coef);
        h = fmaf(dA, h, dv * Bn * xc);

        float v = h * Cn;
        v += __shfl_xor_sync(0xffffffffu, v, 8);
        v += __shfl_xor_sync(0xffffffffu, v, 4);
        v += __shfl_xor_sync(0xffffffffu, v, 2);
        v += __shfl_xor_sync(0xffffffffu, v, 1);

        if (n == 0) {
            float zv = g_xz[bl * (2 * CDIN) + CDIN + d];
            float yv = v + xc * d_skip;
            float sig = 1.f / (1.f + __expf(-zv));
            float yg = yv * (zv * sig);
            g_ygp[bl * CDIN + d] = to_fp16(yg);
        }
    }
}

// ---------------- LayerNorm ----------------
__global__ __launch_bounds__(256)
void ln_kernel(const float* __restrict__ gamma,
               const float* __restrict__ beta,
               float* __restrict__ out)
{
    int row = blockIdx.x;
    const float* p = g_pre + (size_t)row * CD;
    int tid = threadIdx.x;

    float s = 0.f, s2 = 0.f;
    for (int c = tid; c < CD; c += 256) {
        float v = p[c];
        s  += v;
        s2 += v * v;
    }
    #pragma unroll
    for (int o = 16; o >= 1; o >>= 1) {
        s  += __shfl_xor_sync(0xffffffffu, s,  o);
        s2 += __shfl_xor_sync(0xffffffffu, s2, o);
    }
    __shared__ float shs[8], shs2[8];
    int wid = tid >> 5;
    if ((tid & 31) == 0) { shs[wid] = s; shs2[wid] = s2; }
    __syncthreads();
    if (tid < 32) {
        s  = (tid < 8) ? shs[tid]  : 0.f;
        s2 = (tid < 8) ? shs2[tid] : 0.f;
        #pragma unroll
        for (int o = 4; o >= 1; o >>= 1) {
            s  += __shfl_xor_sync(0xffffffffu, s,  o);
            s2 += __shfl_xor_sync(0xffffffffu, s2, o);
        }
        if (tid == 0) { shs[0] = s; shs2[0] = s2; }
    }
    __syncthreads();
    float mean = shs[0] * (1.f / CD);
    float var  = shs2[0] * (1.f / CD) - mean * mean;
    float rstd = rsqrtf(var + CLN_EPS);

    for (int c = tid; c < CD; c += 256) {
        float v = p[c];
        out[(size_t)row * CD + c] = (v - mean) * rstd * gamma[c] + beta[c];
    }
}

// ---------------- launch ----------------
extern "C" void kernel_launch(void* const* d_in, const int* in_sizes, int n_in,
                              void* d_out, int out_size)
{
    const float* x      = (const float*)d_in[0];
    const float* W_in   = (const float*)d_in[1];
    const float* conv_w = (const float*)d_in[2];
    const float* conv_b = (const float*)d_in[3];
    const float* W_x    = (const float*)d_in[4];
    const float* W_dt   = (const float*)d_in[5];
    const float* b_dt   = (const float*)d_in[6];
    const float* A_log  = (const float*)d_in[7];
    const float* D_skip = (const float*)d_in[8];
    const float* W_out  = (const float*)d_in[9];
    const float* ln_g   = (const float*)d_in[10];
    const float* ln_b   = (const float*)d_in[11];
    float* out = (float*)d_out;

    cudaFuncSetAttribute(tgemm4<0>, cudaFuncAttributeMaxDynamicSharedMemorySize, GEMM_SMEM);
    cudaFuncSetAttribute(tgemm4<1>, cudaFuncAttributeMaxDynamicSharedMemorySize, GEMM_SMEM);

    float *p_xz, *p_delta, *p_pre, *p_part;
    uint32_t *p_xp, *p_Winh, *p_Winl, *p_Wxh, *p_Wxl, *p_Wdth, *p_Wdtl, *p_Wouth, *p_Woutl;
    uint16_t *p_xcp, *p_xdp, *p_ygp;
    cudaGetSymbolAddress((void**)&p_xz,    g_xz);
    cudaGetSymbolAddress((void**)&p_delta, g_delta);
    cudaGetSymbolAddress((void**)&p_pre,   g_pre);
    cudaGetSymbolAddress((void**)&p_part,  g_part);
    cudaGetSymbolAddress((void**)&p_xp,    g_xp);
    cudaGetSymbolAddress((void**)&p_Winh,  g_Winp_h);
    cudaGetSymbolAddress((void**)&p_Winl,  g_Winp_l);
    cudaGetSymbolAddress((void**)&p_Wxh,   g_Wxp_h);
    cudaGetSymbolAddress((void**)&p_Wxl,   g_Wxp_l);
    cudaGetSymbolAddress((void**)&p_Wdth,  g_Wdtp_h);
    cudaGetSymbolAddress((void**)&p_Wdtl,  g_Wdtp_l);
    cudaGetSymbolAddress((void**)&p_Wouth, g_Woutp_h);
    cudaGetSymbolAddress((void**)&p_Woutl, g_Woutp_l);
    cudaGetSymbolAddress((void**)&p_xcp,   g_xcp);
    cudaGetSymbolAddress((void**)&p_xdp,   g_xdp);
    cudaGetSymbolAddress((void**)&p_ygp,   g_ygp);

    // pack inputs/weights
    pack_x_kernel<<<(CML*(CD/2) + 255)/256, 256>>>(x);
    pack_w_kernel<<<dim3(CD/64,   (2*CDIN)/32), 256>>>(W_in,  CD,   2*CDIN, p_Winh,  p_Winl);
    pack_w_kernel<<<dim3(CDIN/64, CXD/32),      256>>>(W_x,   CDIN, CXD,    p_Wxh,   p_Wxl);
    pack_w_kernel<<<dim3(CR/64,   CDIN/32),     256>>>(W_dt,  CR,   CDIN,   p_Wdth,  p_Wdtl);
    pack_w_kernel<<<dim3(CDIN/64, CD/32),       256>>>(W_out, CDIN, CD,     p_Wouth, p_Woutl);

    dim3 thr(256);

    // G1: xz = x @ W_in   [2048x1024]x[1024x4096], K=1024 -> 64 tiles
    tgemm4<0><<<dim3((2*CDIN)/128, CML/128), thr, GEMM_SMEM>>>(
        CML, 2*CDIN, p_xp, CD/2, p_Winh, p_Winl, CD/2,
        p_xz, 2*CDIN, nullptr, 0, (CD/2)/8, 0);

    // conv + silu (+ fp16 pack)
    conv_silu_kernel<<<(CML*CDIN + 255)/256, 256>>>(conv_w, conv_b);

    // G2 (split-K x8): x_conv @ W_x -> partials; K chunk 256 -> 16 tiles per z
    tgemm4<0><<<dim3(1, CML/128, KSPL), thr, GEMM_SMEM>>>(
        CML, CXD, (const uint32_t*)p_xcp, CDIN/2, p_Wxh, p_Wxl, CDIN/2,
        p_part, CXD, nullptr, 0, (CDIN/2/KSPL)/8, CDIN/2/KSPL);

    // reduce partials -> xdbl (+ fp16 pack)
    reduce_xdbl_kernel<<<(CML*CXD + 255)/256, 256>>>();

    // G3: delta = softplus(dt @ W_dt + b_dt); K=64 -> 4 tiles
    tgemm4<1><<<dim3(CDIN/128, CML/128), thr, GEMM_SMEM>>>(
        CML, CDIN, (const uint32_t*)p_xdp, CXD/2, p_Wdth, p_Wdtl, CR/2,
        p_delta, CDIN, b_dt, 0, (CR/2)/8, 0);

    // scan (+ skip + gate + fp16 pack)
    scan_kernel<<<(CB*CDIN/2)*32/128, 128>>>(A_log, D_skip);

    // G4: pre = yg @ W_out   [2048x2048]x[2048x1024], K=2048 -> 128 tiles
    tgemm4<0><<<dim3(CD/128, CML/128), thr, GEMM_SMEM>>>(
        CML, CD, (const uint32_t*)p_ygp, CDIN/2, p_Wouth, p_Woutl, CDIN/2,
        p_pre, CD, nullptr, 0, (CDIN/2)/8, 0);

    // LayerNorm
    ln_kernel<<<CML, 256>>>(ln_g, ln_b, out);
}

// round 11
// speedup vs baseline: 1.3999x; 1.3999x over previous
#include <cuda_runtime.h>
#include <cuda_fp16.h>
#include <math.h>
#include <stdint.h>

constexpr int CB   = 2;
constexpr int CL   = 1024;
constexpr int CD   = 1024;
constexpr int CDIN = 2048;
constexpr int CN   = 16;
constexpr int CR   = 64;
constexpr int CK   = 4;
constexpr int CML  = CB * CL;      // 2048
constexpr int CXD  = CR + 2 * CN;  // 96
constexpr int KSPL = 8;
constexpr float CLN_EPS = 1e-5f;

// ---------------- scratch ----------------
__device__ float g_xz   [CML * (2*CDIN)];
__device__ float g_xc   [CML * CDIN];
__device__ float g_xdbl [CML * CXD];
__device__ float g_delta[CML * CDIN];
__device__ float g_pre  [CML * CD];
__device__ float g_part [KSPL * CML * CXD];

__device__ uint32_t g_xp    [CML * (CD/2)];
__device__ uint32_t g_Winp_h[(2*CDIN) * (CD/2)],  g_Winp_l[(2*CDIN) * (CD/2)];
__device__ uint32_t g_Wxp_h [CXD * (CDIN/2)],     g_Wxp_l [CXD * (CDIN/2)];
__device__ uint32_t g_Wdtp_h[CDIN * (CR/2)],      g_Wdtp_l[CDIN * (CR/2)];
__device__ uint32_t g_Woutp_h[CD * (CDIN/2)],     g_Woutp_l[CD * (CDIN/2)];
__device__ uint16_t g_xcp [CML * CDIN];
__device__ uint16_t g_xdp [CML * CXD];
__device__ uint16_t g_ygp [CML * CDIN];

// ---------------- helpers ----------------
__device__ __forceinline__ uint16_t to_fp16(float x)
{
    return __half_as_ushort(__float2half_rn(x));
}

__device__ __forceinline__ void split_fp16(float x, uint16_t& h, uint16_t& l)
{
    __half hh = __float2half_rn(x);
    float r = x - __half2float(hh);
    __half ll = __float2half_rn(r);
    h = __half_as_ushort(hh);
    l = __half_as_ushort(ll);
}

__device__ __forceinline__ void mma_fp16(float* acc, const uint32_t* a, const uint32_t* b)
{
    asm volatile(
        "mma.sync.aligned.m16n8k16.row.col.f32.f16.f16.f32 "
        "{%0,%1,%2,%3}, {%4,%5,%6,%7}, {%8,%9}, {%0,%1,%2,%3};\n"
        : "+f"(acc[0]), "+f"(acc[1]), "+f"(acc[2]), "+f"(acc[3])
        : "r"(a[0]), "r"(a[1]), "r"(a[2]), "r"(a[3]), "r"(b[0]), "r"(b[1]));
}

__device__ __forceinline__ void cp_async16(uint32_t smem_addr, const void* gptr)
{
    asm volatile("cp.async.cg.shared.global [%0], [%1], 16;\n" :: "r"(smem_addr), "l"(gptr));
}

__device__ __forceinline__ uint32_t smem_u32(const void* p)
{
    uint32_t a;
    asm("{ .reg .u64 t; cvta.to.shared.u64 t, %1; cvt.u32.u64 %0, t; }" : "=r"(a) : "l"(p));
    return a;
}

// ---------------- pack x ----------------
__global__ void pack_x_kernel(const float* __restrict__ x)
{
    int i = blockIdx.x * blockDim.x + threadIdx.x;
    if (i >= CML * (CD/2)) return;
    uint16_t h0 = to_fp16(x[2*i]);
    uint16_t h1 = to_fp16(x[2*i + 1]);
    g_xp[i] = (uint32_t)h0 | ((uint32_t)h1 << 16);
}

// ---------------- transpose-pack weight body ----------------
__device__ __forceinline__ void pack_w_body(const float* __restrict__ W, int K, int N,
                                            uint32_t* __restrict__ oh, uint32_t* __restrict__ ol,
                                            int k0, int n0, float (*sm)[33])
{
    int t = threadIdx.x;
    int c = t & 31;
    int r0 = t >> 5;
    #pragma unroll
    for (int it = 0; it < 8; it++) {
        int r = r0 + it * 8;
        sm[r][c] = W[(size_t)(k0 + r) * N + n0 + c];
    }
    __syncthreads();
    int k2 = t & 31;
    int nn0 = t >> 5;
    #pragma unroll
    for (int it = 0; it < 4; it++) {
        int n = nn0 + it * 8;
        float v0 = sm[2*k2    ][n];
        float v1 = sm[2*k2 + 1][n];
        uint16_t h0, l0, h1, l1;
        split_fp16(v0, h0, l0);
        split_fp16(v1, h1, l1);
        size_t o = (size_t)(n0 + n) * (K/2) + k0/2 + k2;
        oh[o] = (uint32_t)h0 | ((uint32_t)h1 << 16);
        ol[o] = (uint32_t)l0 | ((uint32_t)l1 << 16);
    }
}

__global__ void pack_w_kernel(const float* __restrict__ W, int K, int N,
                              uint32_t* __restrict__ oh, uint32_t* __restrict__ ol)
{
    __shared__ float sm[64][33];
    pack_w_body(W, K, N, oh, ol, blockIdx.x * 64, blockIdx.y * 32, sm);
}

// combined pack for Wx, Wdt, Wout: grid (32, 3 + 64 + 32)
__global__ void pack_w3_kernel(const float* __restrict__ Wx,
                               const float* __restrict__ Wdt,
                               const float* __restrict__ Wout,
                               uint32_t* __restrict__ oxh, uint32_t* __restrict__ oxl,
                               uint32_t* __restrict__ odh, uint32_t* __restrict__ odl,
                               uint32_t* __restrict__ ooh, uint32_t* __restrict__ ool)
{
    __shared__ float sm[64][33];
    int gy = blockIdx.y;
    const float* W; int K, N; uint32_t *oh, *ol; int ny;
    if (gy < 3)       { W = Wx;   K = CDIN; N = CXD;  oh = oxh; ol = oxl; ny = gy; }
    else if (gy < 67) { W = Wdt;  K = CR;   N = CDIN; oh = odh; ol = odl; ny = gy - 3; }
    else              { W = Wout; K = CDIN; N = CD;   oh = ooh; ol = ool; ny = gy - 67; }
    int k0 = blockIdx.x * 64;
    if (k0 >= K) return;
    pack_w_body(W, K, N, oh, ol, k0, ny * 32, sm);
}

// ---------------- fp16 tensor-core GEMM, weights 2-term split, BK=32 ----------------
// A single fp16 plane [M][K/2] u32; B hi/lo planes [N][K/2] u32.
// BM=BN=128, BK=32 (16 u32), 256 thr = 8 warps (2x4), warp tile 64x32, 2-stage.
constexpr int BM = 128, BN = 128;
constexpr int STR = 20;                    // u32 per row (16 + pad 4, conflict-free)
constexpr int PLANE = 128 * STR;           // 2560 u32
constexpr int STAGE_U = 3 * PLANE;         // A, Bh, Bl
constexpr int GEMM_SMEM = 2 * STAGE_U * 4; // 61440 bytes

template<int EPI>
__global__ __launch_bounds__(256, 2)
void tgemm5(int M, int N,
            const uint32_t* __restrict__ A_g, int lda2,
            const uint32_t* __restrict__ Bh_g, const uint32_t* __restrict__ Bl_g, int ldb2,
            float* __restrict__ C, int ldc, const float* __restrict__ bias,
            int k2_begin, int ntiles, int zstride)
{
    extern __shared__ uint32_t sm[];

    const int tid  = threadIdx.x;
    const int warp = tid >> 5;
    const int lane = tid & 31;
    const int g    = lane >> 2;
    const int tg   = lane & 3;

    const int row0 = blockIdx.y * BM;
    const int col0 = blockIdx.x * BN;
    const int wm0  = (warp >> 2) * 64;
    const int wn0  = (warp & 3) * 32;

    const int k2b = k2_begin + blockIdx.z * zstride;

    float acc[4][4][4];
    #pragma unroll
    for (int i = 0; i < 4; i++)
        #pragma unroll
        for (int j = 0; j < 4; j++)
            #pragma unroll
            for (int r = 0; r < 4; r++) acc[i][j][r] = 0.f;

    // zero OOB B rows once (B loads are guarded, zeros persist)
    if (N < BN) {
        int nz = BN - N;
        int total = 2 * 2 * nz * 16;   // stages * planes * rows * u32
        for (int idx = tid; idx < total; idx += 256) {
            int lin = idx;
            int w  = lin & 15; lin >>= 4;
            int rq = lin % nz; lin /= nz;
            int pl = lin & 1;  lin >>= 1;
            int sq = lin;
            sm[sq * STAGE_U + (1 + pl) * PLANE + (N + rq) * STR + w] = 0;
        }
    }
    __syncthreads();

    auto load_stage = [&](int stg, int kt) {
        uint32_t* base = sm + stg * STAGE_U;
        const int kcol = k2b + kt * 16;
        #pragma unroll
        for (int i = 0; i < 2; i++) {
            int u = tid + 256 * i;
            int r = u >> 2, c4 = (u & 3) * 4;
            cp_async16(smem_u32(&base[r * STR + c4]),
                       A_g + (size_t)(row0 + r) * lda2 + kcol + c4);
        }
        #pragma unroll
        for (int i = 0; i < 4; i++) {
            int u = tid + 256 * i;
            int pl = u >> 9;
            int v = u & 511;
            int r = v >> 2, c4 = (v & 3) * 4;
            if (col0 + r < N) {
                const uint32_t* src = pl ? Bl_g : Bh_g;
                cp_async16(smem_u32(&base[(1 + pl) * PLANE + r * STR + c4]),
                           src + (size_t)(col0 + r) * ldb2 + kcol + c4);
            }
        }
    };

    load_stage(0, 0);
    asm volatile("cp.async.commit_group;\n" ::: "memory");

    int stg = 0;
    for (int kt = 0; kt < ntiles; kt++) {
        if (kt + 1 < ntiles) {
            load_stage(stg ^ 1, kt + 1);
            asm volatile("cp.async.commit_group;\n" ::: "memory");
            asm volatile("cp.async.wait_group 1;\n" ::: "memory");
        } else {
            asm volatile("cp.async.wait_group 0;\n" ::: "memory");
        }
        __syncthreads();

        const uint32_t* Ap = sm + stg * STAGE_U;
        const uint32_t* Bh = Ap + PLANE;
        const uint32_t* Bl = Ap + 2 * PLANE;

        #pragma unroll
        for (int ks = 0; ks < 2; ks++) {
            const int ko = ks * 8;
            uint32_t af[4][4];
            #pragma unroll
            for (int mt = 0; mt < 4; mt++) {
                int r = wm0 + mt * 16 + g;
                af[mt][0] = Ap[ r      * STR + ko + tg    ];
                af[mt][1] = Ap[(r + 8) * STR + ko + tg    ];
                af[mt][2] = Ap[ r      * STR + ko + tg + 4];
                af[mt][3] = Ap[(r + 8) * STR + ko + tg + 4];
            }
            uint32_t bfh[4][2], bfl[4][2];
            #pragma unroll
            for (int nt = 0; nt < 4; nt++) {
                int c = wn0 + nt * 8 + g;
                bfh[nt][0] = Bh[c * STR + ko + tg    ];
                bfh[nt][1] = Bh[c * STR + ko + tg + 4];
                bfl[nt][0] = Bl[c * STR + ko + tg    ];
                bfl[nt][1] = Bl[c * STR + ko + tg + 4];
            }
            #pragma unroll
            for (int mt = 0; mt < 4; mt++)
                #pragma unroll
                for (int nt = 0; nt < 4; nt++) {
                    mma_fp16(acc[mt][nt], af[mt], bfh[nt]);
                    mma_fp16(acc[mt][nt], af[mt], bfl[nt]);
                }
        }
        __syncthreads();
        stg ^= 1;
    }

    float* Cz = C + (size_t)blockIdx.z * CML * ldc;

    #pragma unroll
    for (int mt = 0; mt < 4; mt++) {
        int r0 = row0 + wm0 + mt * 16 + g;
        #pragma unroll
        for (int nt = 0; nt < 4; nt++) {
            int c0 = col0 + wn0 + nt * 8 + 2 * tg;
            #pragma unroll
            for (int rr = 0; rr < 2; rr++) {
                int r = r0 + rr * 8;
                #pragma unroll
                for (int cc = 0; cc < 2; cc++) {
                    int c = c0 + cc;
                    if (c < N) {
                        float v = acc[mt][nt][rr * 2 + cc];
                        if (EPI == 1) {
                            v = v + bias[c];
                            v = (v > 20.f) ? v : log1pf(__expf(v));
                        }
                        Cz[(size_t)r * ldc + c] = v;
                    }
                }
            }
        }
    }
}

// ---------------- split-K reduce for G2 ----------------
__global__ void reduce_xdbl_kernel()
{
    int i = blockIdx.x * blockDim.x + threadIdx.x;
    if (i >= CML * CXD) return;
    float s = 0.f;
    #pragma unroll
    for (int z = 0; z < KSPL; z++) s += g_part[(size_t)z * CML * CXD + i];
    g_xdbl[i] = s;
    g_xdp[i] = to_fp16(s);
}

// ---------------- conv + SiLU + fp16 pack ----------------
__global__ void conv_silu_kernel(const float* __restrict__ conv_w,
                                 const float* __restrict__ conv_b)
{
    int i = blockIdx.x * blockDim.x + threadIdx.x;
    if (i >= CML * CDIN) return;
    int d  = i & (CDIN - 1);
    int bl = i >> 11;
    int l  = bl & (CL - 1);
    int b  = bl >> 10;

    float acc = conv_b[d];
    #pragma unroll
    for (int k = 0; k < CK; k++) {
        int ll = l - (CK - 1) + k;
        if (ll >= 0) {
            float xin = g_xz[(size_t)(b * CL + ll) * (2 * CDIN) + d];
            acc = fmaf(xin, conv_w[d * CK + k], acc);
        }
    }
    float sig = 1.f / (1.f + __expf(-acc));
    float v = acc * sig;
    g_xc[i] = v;
    g_xcp[i] = to_fp16(v);
}

// ---------------- selective scan ----------------
__global__ __launch_bounds__(128)
void scan_kernel(const float* __restrict__ A_log,
                 const float* __restrict__ D_skip)
{
    int warp = (blockIdx.x * blockDim.x + threadIdx.x) >> 5;
    int lane = threadIdx.x & 31;
    int half = lane >> 4;
    int n    = lane & 15;

    int b = warp >> 10;
    int d = ((warp & 1023) << 1) + half;

    float a_coef = -expf(A_log[d * CN + n]);
    float d_skip = D_skip[d];
    float h = 0.f;

    const size_t bl0 = (size_t)b * CL;
    for (int t = 0; t < CL; t++) {
        size_t bl = bl0 + t;
        float dv = g_delta[bl * CDIN + d];
        float xc = g_xc   [bl * CDIN + d];
        float Bn = g_xdbl [bl * CXD + CR + n];
        float Cn = g_xdbl [bl * CXD + CR + CN + n];

        float dA = __expf(dv * a_coef);
        h = fmaf(dA, h, dv * Bn * xc);

        float v = h * Cn;
        v += __shfl_xor_sync(0xffffffffu, v, 8);
        v += __shfl_xor_sync(0xffffffffu, v, 4);
        v += __shfl_xor_sync(0xffffffffu, v, 2);
        v += __shfl_xor_sync(0xffffffffu, v, 1);

        if (n == 0) {
            float zv = g_xz[bl * (2 * CDIN) + CDIN + d];
            float yv = v + xc * d_skip;
            float sig = 1.f / (1.f + __expf(-zv));
            float yg = yv * (zv * sig);
            g_ygp[bl * CDIN + d] = to_fp16(yg);
        }
    }
}

// ---------------- LayerNorm ----------------
__global__ __launch_bounds__(256)
void ln_kernel(const float* __restrict__ gamma,
               const float* __restrict__ beta,
               float* __restrict__ out)
{
    int row = blockIdx.x;
    const float* p = g_pre + (size_t)row * CD;
    int tid = threadIdx.x;

    float s = 0.f, s2 = 0.f;
    for (int c = tid; c < CD; c += 256) {
        float v = p[c];
        s  += v;
        s2 += v * v;
    }
    #pragma unroll
    for (int o = 16; o >= 1; o >>= 1) {
        s  += __shfl_xor_sync(0xffffffffu, s,  o);
        s2 += __shfl_xor_sync(0xffffffffu, s2, o);
    }
    __shared__ float shs[8], shs2[8];
    int wid = tid >> 5;
    if ((tid & 31) == 0) { shs[wid] = s; shs2[wid] = s2; }
    __syncthreads();
    if (tid < 32) {
        s  = (tid < 8) ? shs[tid]  : 0.f;
        s2 = (tid < 8) ? shs2[tid] : 0.f;
        #pragma unroll
        for (int o = 4; o >= 1; o >>= 1) {
            s  += __shfl_xor_sync(0xffffffffu, s,  o);
            s2 += __shfl_xor_sync(0xffffffffu, s2, o);
        }
        if (tid == 0) { shs[0] = s; shs2[0] = s2; }
    }
    __syncthreads();
    float mean = shs[0] * (1.f / CD);
    float var  = shs2[0] * (1.f / CD) - mean * mean;
    float rstd = rsqrtf(var + CLN_EPS);

    for (int c = tid; c < CD; c += 256) {
        float v = p[c];
        out[(size_t)row * CD + c] = (v - mean) * rstd * gamma[c] + beta[c];
    }
}

// ---------------- launch ----------------
extern "C" void kernel_launch(void* const* d_in, const int* in_sizes, int n_in,
                              void* d_out, int out_size)
{
    const float* x      = (const float*)d_in[0];
    const float* W_in   = (const float*)d_in[1];
    const float* conv_w = (const float*)d_in[2];
    const float* conv_b = (const float*)d_in[3];
    const float* W_x    = (const float*)d_in[4];
    const float* W_dt   = (const float*)d_in[5];
    const float* b_dt   = (const float*)d_in[6];
    const float* A_log  = (const float*)d_in[7];
    const float* D_skip = (const float*)d_in[8];
    const float* W_out  = (const float*)d_in[9];
    const float* ln_g   = (const float*)d_in[10];
    const float* ln_b   = (const float*)d_in[11];
    float* out = (float*)d_out;

    cudaFuncSetAttribute(tgemm5<0>, cudaFuncAttributeMaxDynamicSharedMemorySize, GEMM_SMEM);
    cudaFuncSetAttribute(tgemm5<1>, cudaFuncAttributeMaxDynamicSharedMemorySize, GEMM_SMEM);

    float *p_xz, *p_delta, *p_pre, *p_part;
    uint32_t *p_xp, *p_Winh, *p_Winl, *p_Wxh, *p_Wxl, *p_Wdth, *p_Wdtl, *p_Wouth, *p_Woutl;
    uint16_t *p_xcp, *p_xdp, *p_ygp;
    cudaGetSymbolAddress((void**)&p_xz,    g_xz);
    cudaGetSymbolAddress((void**)&p_delta, g_delta);
    cudaGetSymbolAddress((void**)&p_pre,   g_pre);
    cudaGetSymbolAddress((void**)&p_part,  g_part);
    cudaGetSymbolAddress((void**)&p_xp,    g_xp);
    cudaGetSymbolAddress((void**)&p_Winh,  g_Winp_h);
    cudaGetSymbolAddress((void**)&p_Winl,  g_Winp_l);
    cudaGetSymbolAddress((void**)&p_Wxh,   g_Wxp_h);
    cudaGetSymbolAddress((void**)&p_Wxl,   g_Wxp_l);
    cudaGetSymbolAddress((void**)&p_Wdth,  g_Wdtp_h);
    cudaGetSymbolAddress((void**)&p_Wdtl,  g_Wdtp_l);
    cudaGetSymbolAddress((void**)&p_Wouth, g_Woutp_h);
    cudaGetSymbolAddress((void**)&p_Woutl, g_Woutp_l);
    cudaGetSymbolAddress((void**)&p_xcp,   g_xcp);
    cudaGetSymbolAddress((void**)&p_xdp,   g_xdp);
    cudaGetSymbolAddress((void**)&p_ygp,   g_ygp);

    // launches 1-3: packs (G1 is 4th -> ncu capture target)
    pack_x_kernel<<<(CML*(CD/2) + 255)/256, 256>>>(x);
    pack_w_kernel<<<dim3(CD/64, (2*CDIN)/32), 256>>>(W_in, CD, 2*CDIN, p_Winh, p_Winl);
    pack_w3_kernel<<<dim3(CDIN/64, 3 + CDIN/32 + CD/32), 256>>>(
        W_x, W_dt, W_out, p_Wxh, p_Wxl, p_Wdth, p_Wdtl, p_Wouth, p_Woutl);

    dim3 thr(256);

    // G1: xz = x @ W_in; K=1024 -> 32 BK32 tiles   (launch #4: profiled)
    tgemm5<0><<<dim3((2*CDIN)/128, CML/128), thr, GEMM_SMEM>>>(
        CML, 2*CDIN, p_xp, CD/2, p_Winh, p_Winl, CD/2,
        p_xz, 2*CDIN, nullptr, 0, (CD/2)/16, 0);

    // conv + silu (+ fp16 pack)
    conv_silu_kernel<<<(CML*CDIN + 255)/256, 256>>>(conv_w, conv_b);

    // G2 (split-K x8): K chunk 256 -> 8 tiles per z
    tgemm5<0><<<dim3(1, CML/128, KSPL), thr, GEMM_SMEM>>>(
        CML, CXD, (const uint32_t*)p_xcp, CDIN/2, p_Wxh, p_Wxl, CDIN/2,
        p_part, CXD, nullptr, 0, (CDIN/2/KSPL)/16, CDIN/2/KSPL);

    // reduce partials -> xdbl (+ fp16 pack)
    reduce_xdbl_kernel<<<(CML*CXD + 255)/256, 256>>>();

    // G3: delta = softplus(dt @ W_dt + b_dt); K=64 -> 2 tiles
    tgemm5<1><<<dim3(CDIN/128, CML/128), thr, GEMM_SMEM>>>(
        CML, CDIN, (const uint32_t*)p_xdp, CXD/2, p_Wdth, p_Wdtl, CR/2,
        p_delta, CDIN, b_dt, 0, (CR/2)/16, 0);

    // scan (+ skip + gate + fp16 pack)
    scan_kernel<<<(CB*CDIN/2)*32/128, 128>>>(A_log, D_skip);

    // G4: pre = yg @ W_out; K=2048 -> 64 tiles
    tgemm5<0><<<dim3(CD/128, CML/128), thr, GEMM_SMEM>>>(
        CML, CD, (const uint32_t*)p_ygp, CDIN/2, p_Wouth, p_Woutl, CDIN/2,
        p_pre, CD, nullptr, 0, (CDIN/2)/16, 0);

    // LayerNorm
    ln_kernel<<<CML, 256>>>(ln_g, ln_b, out);
}

// round 12
// speedup vs baseline: 3.3216x; 2.3728x over previous
#include <cuda_runtime.h>
#include <cuda_fp16.h>
#include <math.h>
#include <stdint.h>

constexpr int CB   = 2;
constexpr int CL   = 1024;
constexpr int CD   = 1024;
constexpr int CDIN = 2048;
constexpr int CN   = 16;
constexpr int CR   = 64;
constexpr int CK   = 4;
constexpr int CML  = CB * CL;      // 2048
constexpr int CXD  = CR + 2 * CN;  // 96
constexpr int KSPL = 8;
constexpr float CLN_EPS = 1e-5f;

// ---------------- scratch ----------------
__device__ float g_xz   [CML * (2*CDIN)];
__device__ float g_xc   [CML * CDIN];
__device__ float g_xdbl [CML * CXD];
__device__ float g_delta[CML * CDIN];
__device__ float g_y    [CML * CDIN];     // raw scan output (pre-gate)
__device__ float g_pre  [CML * CD];
__device__ float g_part [KSPL * CML * CXD];

__device__ uint32_t g_xp    [CML * (CD/2)];
__device__ uint32_t g_Winp_h[(2*CDIN) * (CD/2)],  g_Winp_l[(2*CDIN) * (CD/2)];
__device__ uint32_t g_Wxp_h [CXD * (CDIN/2)],     g_Wxp_l [CXD * (CDIN/2)];
__device__ uint32_t g_Wdtp_h[CDIN * (CR/2)],      g_Wdtp_l[CDIN * (CR/2)];
__device__ uint32_t g_Woutp_h[CD * (CDIN/2)],     g_Woutp_l[CD * (CDIN/2)];
__device__ uint16_t g_xcp [CML * CDIN];
__device__ uint16_t g_xdp [CML * CXD];
__device__ uint16_t g_ygp [CML * CDIN];

// ---------------- helpers ----------------
__device__ __forceinline__ uint16_t to_fp16(float x)
{
    return __half_as_ushort(__float2half_rn(x));
}

__device__ __forceinline__ void split_fp16(float x, uint16_t& h, uint16_t& l)
{
    __half hh = __float2half_rn(x);
    float r = x - __half2float(hh);
    __half ll = __float2half_rn(r);
    h = __half_as_ushort(hh);
    l = __half_as_ushort(ll);
}

__device__ __forceinline__ void mma_fp16(float* acc, const uint32_t* a, const uint32_t* b)
{
    asm volatile(
        "mma.sync.aligned.m16n8k16.row.col.f32.f16.f16.f32 "
        "{%0,%1,%2,%3}, {%4,%5,%6,%7}, {%8,%9}, {%0,%1,%2,%3};\n"
        : "+f"(acc[0]), "+f"(acc[1]), "+f"(acc[2]), "+f"(acc[3])
        : "r"(a[0]), "r"(a[1]), "r"(a[2]), "r"(a[3]), "r"(b[0]), "r"(b[1]));
}

__device__ __forceinline__ void cp_async16(uint32_t smem_addr, const void* gptr)
{
    asm volatile("cp.async.cg.shared.global [%0], [%1], 16;\n" :: "r"(smem_addr), "l"(gptr));
}

__device__ __forceinline__ uint32_t smem_u32(const void* p)
{
    uint32_t a;
    asm("{ .reg .u64 t; cvta.to.shared.u64 t, %1; cvt.u32.u64 %0, t; }" : "=r"(a) : "l"(p));
    return a;
}

// ---------------- pack x ----------------
__global__ void pack_x_kernel(const float* __restrict__ x)
{
    int i = blockIdx.x * blockDim.x + threadIdx.x;
    if (i >= CML * (CD/2)) return;
    uint16_t h0 = to_fp16(x[2*i]);
    uint16_t h1 = to_fp16(x[2*i + 1]);
    g_xp[i] = (uint32_t)h0 | ((uint32_t)h1 << 16);
}

// ---------------- transpose-pack weight body ----------------
__device__ __forceinline__ void pack_w_body(const float* __restrict__ W, int K, int N,
                                            uint32_t* __restrict__ oh, uint32_t* __restrict__ ol,
                                            int k0, int n0, float (*sm)[33])
{
    int t = threadIdx.x;
    int c = t & 31;
    int r0 = t >> 5;
    #pragma unroll
    for (int it = 0; it < 8; it++) {
        int r = r0 + it * 8;
        sm[r][c] = W[(size_t)(k0 + r) * N + n0 + c];
    }
    __syncthreads();
    int k2 = t & 31;
    int nn0 = t >> 5;
    #pragma unroll
    for (int it = 0; it < 4; it++) {
        int n = nn0 + it * 8;
        float v0 = sm[2*k2    ][n];
        float v1 = sm[2*k2 + 1][n];
        uint16_t h0, l0, h1, l1;
        split_fp16(v0, h0, l0);
        split_fp16(v1, h1, l1);
        size_t o = (size_t)(n0 + n) * (K/2) + k0/2 + k2;
        oh[o] = (uint32_t)h0 | ((uint32_t)h1 << 16);
        ol[o] = (uint32_t)l0 | ((uint32_t)l1 << 16);
    }
}

__global__ void pack_w_kernel(const float* __restrict__ W, int K, int N,
                              uint32_t* __restrict__ oh, uint32_t* __restrict__ ol)
{
    __shared__ float sm[64][33];
    pack_w_body(W, K, N, oh, ol, blockIdx.x * 64, blockIdx.y * 32, sm);
}

__global__ void pack_w3_kernel(const float* __restrict__ Wx,
                               const float* __restrict__ Wdt,
                               const float* __restrict__ Wout,
                               uint32_t* __restrict__ oxh, uint32_t* __restrict__ oxl,
                               uint32_t* __restrict__ odh, uint32_t* __restrict__ odl,
                               uint32_t* __restrict__ ooh, uint32_t* __restrict__ ool)
{
    __shared__ float sm[64][33];
    int gy = blockIdx.y;
    const float* W; int K, N; uint32_t *oh, *ol; int ny;
    if (gy < 3)       { W = Wx;   K = CDIN; N = CXD;  oh = oxh; ol = oxl; ny = gy; }
    else if (gy < 67) { W = Wdt;  K = CR;   N = CDIN; oh = odh; ol = odl; ny = gy - 3; }
    else              { W = Wout; K = CDIN; N = CD;   oh = ooh; ol = ool; ny = gy - 67; }
    int k0 = blockIdx.x * 64;
    if (k0 >= K) return;
    pack_w_body(W, K, N, oh, ol, k0, ny * 32, sm);
}

// ---------------- fp16 tensor-core GEMM (unchanged from R11) ----------------
constexpr int BM = 128, BN = 128;
constexpr int STR = 20;
constexpr int PLANE = 128 * STR;
constexpr int STAGE_U = 3 * PLANE;
constexpr int GEMM_SMEM = 2 * STAGE_U * 4;

template<int EPI>
__global__ __launch_bounds__(256, 2)
void tgemm5(int M, int N,
            const uint32_t* __restrict__ A_g, int lda2,
            const uint32_t* __restrict__ Bh_g, const uint32_t* __restrict__ Bl_g, int ldb2,
            float* __restrict__ C, int ldc, const float* __restrict__ bias,
            int k2_begin, int ntiles, int zstride)
{
    extern __shared__ uint32_t sm[];

    const int tid  = threadIdx.x;
    const int warp = tid >> 5;
    const int lane = tid & 31;
    const int g    = lane >> 2;
    const int tg   = lane & 3;

    const int row0 = blockIdx.y * BM;
    const int col0 = blockIdx.x * BN;
    const int wm0  = (warp >> 2) * 64;
    const int wn0  = (warp & 3) * 32;

    const int k2b = k2_begin + blockIdx.z * zstride;

    float acc[4][4][4];
    #pragma unroll
    for (int i = 0; i < 4; i++)
        #pragma unroll
        for (int j = 0; j < 4; j++)
            #pragma unroll
            for (int r = 0; r < 4; r++) acc[i][j][r] = 0.f;

    if (N < BN) {
        int nz = BN - N;
        int total = 2 * 2 * nz * 16;
        for (int idx = tid; idx < total; idx += 256) {
            int lin = idx;
            int w  = lin & 15; lin >>= 4;
            int rq = lin % nz; lin /= nz;
            int pl = lin & 1;  lin >>= 1;
            int sq = lin;
            sm[sq * STAGE_U + (1 + pl) * PLANE + (N + rq) * STR + w] = 0;
        }
    }
    __syncthreads();

    auto load_stage = [&](int stg, int kt) {
        uint32_t* base = sm + stg * STAGE_U;
        const int kcol = k2b + kt * 16;
        #pragma unroll
        for (int i = 0; i < 2; i++) {
            int u = tid + 256 * i;
            int r = u >> 2, c4 = (u & 3) * 4;
            cp_async16(smem_u32(&base[r * STR + c4]),
                       A_g + (size_t)(row0 + r) * lda2 + kcol + c4);
        }
        #pragma unroll
        for (int i = 0; i < 4; i++) {
            int u = tid + 256 * i;
            int pl = u >> 9;
            int v = u & 511;
            int r = v >> 2, c4 = (v & 3) * 4;
            if (col0 + r < N) {
                const uint32_t* src = pl ? Bl_g : Bh_g;
                cp_async16(smem_u32(&base[(1 + pl) * PLANE + r * STR + c4]),
                           src + (size_t)(col0 + r) * ldb2 + kcol + c4);
            }
        }
    };

    load_stage(0, 0);
    asm volatile("cp.async.commit_group;\n" ::: "memory");

    int stg = 0;
    for (int kt = 0; kt < ntiles; kt++) {
        if (kt + 1 < ntiles) {
            load_stage(stg ^ 1, kt + 1);
            asm volatile("cp.async.commit_group;\n" ::: "memory");
            asm volatile("cp.async.wait_group 1;\n" ::: "memory");
        } else {
            asm volatile("cp.async.wait_group 0;\n" ::: "memory");
        }
        __syncthreads();

        const uint32_t* Ap = sm + stg * STAGE_U;
        const uint32_t* Bh = Ap + PLANE;
        const uint32_t* Bl = Ap + 2 * PLANE;

        #pragma unroll
        for (int ks = 0; ks < 2; ks++) {
            const int ko = ks * 8;
            uint32_t af[4][4];
            #pragma unroll
            for (int mt = 0; mt < 4; mt++) {
                int r = wm0 + mt * 16 + g;
                af[mt][0] = Ap[ r      * STR + ko + tg    ];
                af[mt][1] = Ap[(r + 8) * STR + ko + tg    ];
                af[mt][2] = Ap[ r      * STR + ko + tg + 4];
                af[mt][3] = Ap[(r + 8) * STR + ko + tg + 4];
            }
            uint32_t bfh[4][2], bfl[4][2];
            #pragma unroll
            for (int nt = 0; nt < 4; nt++) {
                int c = wn0 + nt * 8 + g;
                bfh[nt][0] = Bh[c * STR + ko + tg    ];
                bfh[nt][1] = Bh[c * STR + ko + tg + 4];
                bfl[nt][0] = Bl[c * STR + ko + tg    ];
                bfl[nt][1] = Bl[c * STR + ko + tg + 4];
            }
            #pragma unroll
            for (int mt = 0; mt < 4; mt++)
                #pragma unroll
                for (int nt = 0; nt < 4; nt++) {
                    mma_fp16(acc[mt][nt], af[mt], bfh[nt]);
                    mma_fp16(acc[mt][nt], af[mt], bfl[nt]);
                }
        }
        __syncthreads();
        stg ^= 1;
    }

    float* Cz = C + (size_t)blockIdx.z * CML * ldc;

    #pragma unroll
    for (int mt = 0; mt < 4; mt++) {
        int r0 = row0 + wm0 + mt * 16 + g;
        #pragma unroll
        for (int nt = 0; nt < 4; nt++) {
            int c0 = col0 + wn0 + nt * 8 + 2 * tg;
            #pragma unroll
            for (int rr = 0; rr < 2; rr++) {
                int r = r0 + rr * 8;
                #pragma unroll
                for (int cc = 0; cc < 2; cc++) {
                    int c = c0 + cc;
                    if (c < N) {
                        float v = acc[mt][nt][rr * 2 + cc];
                        if (EPI == 1) {
                            v = v + bias[c];
                            v = (v > 20.f) ? v : log1pf(__expf(v));
                        }
                        Cz[(size_t)r * ldc + c] = v;
                    }
                }
            }
        }
    }
}

// ---------------- split-K reduce for G2 ----------------
__global__ void reduce_xdbl_kernel(const float* __restrict__ part,
                                   float* __restrict__ xdbl,
                                   uint16_t* __restrict__ xdp)
{
    int i = blockIdx.x * blockDim.x + threadIdx.x;
    if (i >= CML * CXD) return;
    float s = 0.f;
    #pragma unroll
    for (int z = 0; z < KSPL; z++) s += part[(size_t)z * CML * CXD + i];
    xdbl[i] = s;
    xdp[i] = to_fp16(s);
}

// ---------------- conv + SiLU + fp16 pack ----------------
__global__ void conv_silu_kernel(const float* __restrict__ xz,
                                 const float* __restrict__ conv_w,
                                 const float* __restrict__ conv_b,
                                 float* __restrict__ xc,
                                 uint16_t* __restrict__ xcp)
{
    int i = blockIdx.x * blockDim.x + threadIdx.x;
    if (i >= CML * CDIN) return;
    int d  = i & (CDIN - 1);
    int bl = i >> 11;
    int l  = bl & (CL - 1);
    int b  = bl >> 10;

    float acc = conv_b[d];
    #pragma unroll
    for (int k = 0; k < CK; k++) {
        int ll = l - (CK - 1) + k;
        if (ll >= 0) {
            float xin = xz[(size_t)(b * CL + ll) * (2 * CDIN) + d];
            acc = fmaf(xin, conv_w[d * CK + k], acc);
        }
    }
    float sig = 1.f / (1.f + __expf(-acc));
    float v = acc * sig;
    xc[i] = v;
    xcp[i] = to_fp16(v);
}

// ---------------- selective scan: restrict + 4x unrolled prefetch ----------------
// warp = 2 channels x 16 states. Stores raw y (pre-gate); gate in separate kernel.
__global__ __launch_bounds__(128)
void scan_kernel(const float* __restrict__ delta,
                 const float* __restrict__ xc,
                 const float* __restrict__ xdbl,
                 const float* __restrict__ A_log,
                 const float* __restrict__ D_skip,
                 float* __restrict__ yout)
{
    int warp = (blockIdx.x * blockDim.x + threadIdx.x) >> 5;
    int lane = threadIdx.x & 31;
    int half = lane >> 4;
    int n    = lane & 15;

    int b = warp >> 10;
    int d = ((warp & 1023) << 1) + half;

    float a_coef = -expf(A_log[d * CN + n]);
    float d_skip = D_skip[d];
    float h = 0.f;

    const size_t bl0 = (size_t)b * CL;
    for (int t = 0; t < CL; t += 4) {
        float dv[4], xv[4], Bn[4], Cn[4];
        #pragma unroll
        for (int u = 0; u < 4; u++) {
            size_t bl = bl0 + t + u;
            dv[u] = delta[bl * CDIN + d];
            xv[u] = xc   [bl * CDIN + d];
            Bn[u] = xdbl [bl * CXD + CR + n];
            Cn[u] = xdbl [bl * CXD + CR + CN + n];
        }
        #pragma unroll
        for (int u = 0; u < 4; u++) {
            float dA = __expf(dv[u] * a_coef);
            h = fmaf(dA, h, dv[u] * Bn[u] * xv[u]);

            float v = h * Cn[u];
            v += __shfl_xor_sync(0xffffffffu, v, 8);
            v += __shfl_xor_sync(0xffffffffu, v, 4);
            v += __shfl_xor_sync(0xffffffffu, v, 2);
            v += __shfl_xor_sync(0xffffffffu, v, 1);

            if (n == 0)
                yout[(bl0 + t + u) * CDIN + d] = v + xv[u] * d_skip;
        }
    }
}

// ---------------- gate + fp16 pack (coalesced) ----------------
__global__ void gate_pack_kernel(const float* __restrict__ y,
                                 const float* __restrict__ xz,
                                 uint16_t* __restrict__ ygp)
{
    int i = blockIdx.x * blockDim.x + threadIdx.x;
    if (i >= CML * CDIN) return;
    int d  = i & (CDIN - 1);
    int bl = i >> 11;
    float zv = xz[(size_t)bl * (2 * CDIN) + CDIN + d];
    float sig = 1.f / (1.f + __expf(-zv));
    ygp[i] = to_fp16(y[i] * (zv * sig));
}

// ---------------- LayerNorm ----------------
__global__ __launch_bounds__(256)
void ln_kernel(const float* __restrict__ pre,
               const float* __restrict__ gamma,
               const float* __restrict__ beta,
               float* __restrict__ out)
{
    int row = blockIdx.x;
    const float* p = pre + (size_t)row * CD;
    int tid = threadIdx.x;

    float s = 0.f, s2 = 0.f;
    for (int c = tid; c < CD; c += 256) {
        float v = p[c];
        s  += v;
        s2 += v * v;
    }
    #pragma unroll
    for (int o = 16; o >= 1; o >>= 1) {
        s  += __shfl_xor_sync(0xffffffffu, s,  o);
        s2 += __shfl_xor_sync(0xffffffffu, s2, o);
    }
    __shared__ float shs[8], shs2[8];
    int wid = tid >> 5;
    if ((tid & 31) == 0) { shs[wid] = s; shs2[wid] = s2; }
    __syncthreads();
    if (tid < 32) {
        s  = (tid < 8) ? shs[tid]  : 0.f;
        s2 = (tid < 8) ? shs2[tid] : 0.f;
        #pragma unroll
        for (int o = 4; o >= 1; o >>= 1) {
            s  += __shfl_xor_sync(0xffffffffu, s,  o);
            s2 += __shfl_xor_sync(0xffffffffu, s2, o);
        }
        if (tid == 0) { shs[0] = s; shs2[0] = s2; }
    }
    __syncthreads();
    float mean = shs[0] * (1.f / CD);
    float var  = shs2[0] * (1.f / CD) - mean * mean;
    float rstd = rsqrtf(var + CLN_EPS);

    for (int c = tid; c < CD; c += 256) {
        float v = p[c];
        out[(size_t)row * CD + c] = (v - mean) * rstd * gamma[c] + beta[c];
    }
}

// ---------------- launch ----------------
extern "C" void kernel_launch(void* const* d_in, const int* in_sizes, int n_in,
                              void* d_out, int out_size)
{
    const float* x      = (const float*)d_in[0];
    const float* W_in   = (const float*)d_in[1];
    const float* conv_w = (const float*)d_in[2];
    const float* conv_b = (const float*)d_in[3];
    const float* W_x    = (const float*)d_in[4];
    const float* W_dt   = (const float*)d_in[5];
    const float* b_dt   = (const float*)d_in[6];
    const float* A_log  = (const float*)d_in[7];
    const float* D_skip = (const float*)d_in[8];
    const float* W_out  = (const float*)d_in[9];
    const float* ln_g   = (const float*)d_in[10];
    const float* ln_b   = (const float*)d_in[11];
    float* out = (float*)d_out;

    cudaFuncSetAttribute(tgemm5<0>, cudaFuncAttributeMaxDynamicSharedMemorySize, GEMM_SMEM);
    cudaFuncSetAttribute(tgemm5<1>, cudaFuncAttributeMaxDynamicSharedMemorySize, GEMM_SMEM);

    float *p_xz, *p_xc, *p_xdbl, *p_delta, *p_y, *p_pre, *p_part;
    uint32_t *p_xp, *p_Winh, *p_Winl, *p_Wxh, *p_Wxl, *p_Wdth, *p_Wdtl, *p_Wouth, *p_Woutl;
    uint16_t *p_xcp, *p_xdp, *p_ygp;
    cudaGetSymbolAddress((void**)&p_xz,    g_xz);
    cudaGetSymbolAddress((void**)&p_xc,    g_xc);
    cudaGetSymbolAddress((void**)&p_xdbl,  g_xdbl);
    cudaGetSymbolAddress((void**)&p_delta, g_delta);
    cudaGetSymbolAddress((void**)&p_y,     g_y);
    cudaGetSymbolAddress((void**)&p_pre,   g_pre);
    cudaGetSymbolAddress((void**)&p_part,  g_part);
    cudaGetSymbolAddress((void**)&p_xp,    g_xp);
    cudaGetSymbolAddress((void**)&p_Winh,  g_Winp_h);
    cudaGetSymbolAddress((void**)&p_Winl,  g_Winp_l);
    cudaGetSymbolAddress((void**)&p_Wxh,   g_Wxp_h);
    cudaGetSymbolAddress((void**)&p_Wxl,   g_Wxp_l);
    cudaGetSymbolAddress((void**)&p_Wdth,  g_Wdtp_h);
    cudaGetSymbolAddress((void**)&p_Wdtl,  g_Wdtp_l);
    cudaGetSymbolAddress((void**)&p_Wouth, g_Woutp_h);
    cudaGetSymbolAddress((void**)&p_Woutl, g_Woutp_l);
    cudaGetSymbolAddress((void**)&p_xcp,   g_xcp);
    cudaGetSymbolAddress((void**)&p_xdp,   g_xdp);
    cudaGetSymbolAddress((void**)&p_ygp,   g_ygp);

    pack_x_kernel<<<(CML*(CD/2) + 255)/256, 256>>>(x);
    pack_w_kernel<<<dim3(CD/64, (2*CDIN)/32), 256>>>(W_in, CD, 2*CDIN, p_Winh, p_Winl);
    pack_w3_kernel<<<dim3(CDIN/64, 3 + CDIN/32 + CD/32), 256>>>(
        W_x, W_dt, W_out, p_Wxh, p_Wxl, p_Wdth, p_Wdtl, p_Wouth, p_Woutl);

    dim3 thr(256);

    // G1 (launch #4 -> profiled)
    tgemm5<0><<<dim3((2*CDIN)/128, CML/128), thr, GEMM_SMEM>>>(
        CML, 2*CDIN, p_xp, CD/2, p_Winh, p_Winl, CD/2,
        p_xz, 2*CDIN, nullptr, 0, (CD/2)/16, 0);

    conv_silu_kernel<<<(CML*CDIN + 255)/256, 256>>>(p_xz, conv_w, conv_b, p_xc, p_xcp);

    tgemm5<0><<<dim3(1, CML/128, KSPL), thr, GEMM_SMEM>>>(
        CML, CXD, (const uint32_t*)p_xcp, CDIN/2, p_Wxh, p_Wxl, CDIN/2,
        p_part, CXD, nullptr, 0, (CDIN/2/KSPL)/16, CDIN/2/KSPL);

    reduce_xdbl_kernel<<<(CML*CXD + 255)/256, 256>>>(p_part, p_xdbl, p_xdp);

    tgemm5<1><<<dim3(CDIN/128, CML/128), thr, GEMM_SMEM>>>(
        CML, CDIN, (const uint32_t*)p_xdp, CXD/2, p_Wdth, p_Wdtl, CR/2,
        p_delta, CDIN, b_dt, 0, (CR/2)/16, 0);

    scan_kernel<<<(CB*CDIN/2)*32/128, 128>>>(p_delta, p_xc, p_xdbl, A_log, D_skip, p_y);

    gate_pack_kernel<<<(CML*CDIN + 255)/256, 256>>>(p_y, p_xz, p_ygp);

    tgemm5<0><<<dim3(CD/128, CML/128), thr, GEMM_SMEM>>>(
        CML, CD, (const uint32_t*)p_ygp, CDIN/2, p_Wouth, p_Woutl, CDIN/2,
        p_pre, CD, nullptr, 0, (CDIN/2)/16, 0);

    ln_kernel<<<CML, 256>>>(p_pre, ln_g, ln_b, out);
}